// round 16
// baseline (speedup 1.0000x reference)
#include <cuda_runtime.h>
#include <math.h>

#define NTOT   32768
#define EDG    524288
#define HD     256
#define HEADS  8
#define CDIM   32
#define GRAPHS 64
#define NPG    512
#define CAP    128

// ----------------------------- scratch (static device) -----------------------------
__device__ __align__(16) float g_xl[NTOT*HD];
__device__ __align__(16) float g_xr[NTOT*HD];
__device__ __align__(16) float g_qkv[NTOT*3*HD];
__device__ __align__(16) float g_attno[NTOT*HD];   // A-perm
__device__ __align__(16) float g_graw[NTOT*HD];
__device__ __align__(16) float g_local[NTOT*HD];
__device__ __align__(16) float g_comb[NTOT*HD];    // A-perm
__device__ __align__(16) float g_h1[NTOT*4*HD];    // A-perm
__device__ __align__(16) float g_f2[NTOT*HD];
__device__ __align__(16) float g_rx[NTOT*HD];      // A-perm
__device__ __align__(16) float g_rwl[HD*HD];       // B-perm
__device__ __align__(16) float g_rwr[HD*HD];
__device__ __align__(16) float g_ripw[3*HD*HD];
__device__ __align__(16) float g_ropw[HD*HD];
__device__ __align__(16) float g_rw1[HD*4*HD];
__device__ __align__(16) float g_rw2[4*HD*HD];
__device__ int   g_deg[NTOT];
__device__ int   g_off[NTOT];
__device__ int   g_cur[NTOT];
__device__ int   g_csr[EDG];
__device__ float g_easum[NTOT*2];

// ----------------------------- helpers -----------------------------
__device__ __forceinline__ unsigned tf32cvt(float f){
    unsigned r;
    asm("cvt.rna.tf32.f32 %0,%1;" : "=r"(r) : "f"(f));
    return r;
}
__device__ __forceinline__ float tf32round(float f){
    return __uint_as_float(tf32cvt(f));
}
__device__ __forceinline__ void mma_tf32(float* c, const unsigned* a, unsigned b0, unsigned b1){
    asm volatile(
        "mma.sync.aligned.m16n8k8.row.col.f32.tf32.tf32.f32 "
        "{%0,%1,%2,%3},{%4,%5,%6,%7},{%8,%9},{%0,%1,%2,%3};"
        : "+f"(c[0]), "+f"(c[1]), "+f"(c[2]), "+f"(c[3])
        : "r"(a[0]), "r"(a[1]), "r"(a[2]), "r"(a[3]), "r"(b0), "r"(b1));
}
__device__ __forceinline__ void cpa16(unsigned dst, const void* src){
    asm volatile("cp.async.cg.shared.global [%0], [%1], 16;" :: "r"(dst), "l"(src));
}
__device__ __forceinline__ float geluf(float x){
    return 0.5f * x * (1.0f + erff(x * 0.70710678118654752f));
}
// A-perm: block(m>>4, k>>3) of 128 words; word = ((m&7)*4 + (k&3))*4 + ((m>>3)&1) + 2*((k>>2)&1)
__device__ __forceinline__ size_t aperm(int m, int k, int K){
    return (size_t)((m >> 4) * (K >> 3) + (k >> 3)) * 128
         + ((m & 7) * 4 + (k & 3)) * 4 + ((m >> 3) & 1) + (((k >> 2) & 1) << 1);
}
__device__ __forceinline__ float warpsum(float v){
    #pragma unroll
    for (int o = 16; o; o >>= 1) v += __shfl_xor_sync(0xffffffffu, v, o);
    return v;
}

// ----------------------------- repack kernels -----------------------------
__global__ void k_repa(const float* __restrict__ in, float* __restrict__ outp, int M, int K){
    int i = blockIdx.x * blockDim.x + threadIdx.x;
    if (i >= M * (K >> 2)) return;
    int m = i / (K >> 2), kq = i % (K >> 2);
    float4 v = ((const float4*)in)[(size_t)m * (K >> 2) + kq];
    size_t base = (size_t)((m >> 4) * (K >> 3) + (kq >> 1)) * 128
                + ((m & 7) * 4) * 4 + ((m >> 3) & 1) + ((kq & 1) << 1);
    outp[base +  0] = tf32round(v.x);
    outp[base +  4] = tf32round(v.y);
    outp[base +  8] = tf32round(v.z);
    outp[base + 12] = tf32round(v.w);
}
template<bool SRC_TB>
__global__ void k_repb(const float* __restrict__ in, float* __restrict__ outp, int N, int K){
    int w2 = blockIdx.x * blockDim.x + threadIdx.x;
    if (w2 >= (N * K) >> 1) return;
    int blk = w2 >> 5, pi = w2 & 31;
    int n7 = pi >> 2, k3 = pi & 3;
    int nb = blk / (K >> 3), k8 = blk % (K >> 3);
    int n = nb * 8 + n7;
    int ka = k8 * 8 + k3, kb = ka + 4;
    float va, vb;
    if (SRC_TB) { va = in[(size_t)n * K + ka]; vb = in[(size_t)n * K + kb]; }
    else        { va = in[(size_t)ka * N + n]; vb = in[(size_t)kb * N + n]; }
    float2 o = { tf32round(va), tf32round(vb) };
    *(float2*)&outp[(size_t)w2 * 2] = o;
}

// ----------------------------- tiny graph kernels -----------------------------
__global__ void k_zero(){
    int i = blockIdx.x * blockDim.x + threadIdx.x;
    if (i < NTOT) { g_deg[i] = 0; g_cur[i] = 0; g_easum[2*i] = 0.f; g_easum[2*i+1] = 0.f; }
}
__global__ void k_edgecnt(const int* __restrict__ ei, const float* __restrict__ ea){
    int e = blockIdx.x * blockDim.x + threadIdx.x;
    if (e < EDG) {
        int d = ei[EDG + e];
        atomicAdd(&g_deg[d], 1);
        atomicAdd(&g_easum[2*d],     ea[2*e]);
        atomicAdd(&g_easum[2*d + 1], ea[2*e + 1]);
    }
}
__global__ void k_scan(){
    __shared__ int wsum[32];
    int tid = threadIdx.x;
    int base = tid * 32;
    int loc[32]; int s = 0;
    #pragma unroll
    for (int t = 0; t < 32; t++) { loc[t] = s; s += g_deg[base + t]; }
    int lane = tid & 31, wid = tid >> 5;
    int v = s;
    #pragma unroll
    for (int o = 1; o < 32; o <<= 1) { int n = __shfl_up_sync(0xffffffffu, v, o); if (lane >= o) v += n; }
    if (lane == 31) wsum[wid] = v;
    __syncthreads();
    if (wid == 0) {
        int w = wsum[lane];
        #pragma unroll
        for (int o = 1; o < 32; o <<= 1) { int n = __shfl_up_sync(0xffffffffu, w, o); if (lane >= o) w += n; }
        wsum[lane] = w;
    }
    __syncthreads();
    int chunk_base = v - s + (wid ? wsum[wid - 1] : 0);
    #pragma unroll
    for (int t = 0; t < 32; t++) g_off[base + t] = chunk_base + loc[t];
}
__global__ void k_fill(const int* __restrict__ ei){
    int e = blockIdx.x * blockDim.x + threadIdx.x;
    if (e < EDG) {
        int d = ei[EDG + e];
        int p = atomicAdd(&g_cur[d], 1);
        g_csr[g_off[d] + p] = e;
    }
}

// ----------------------------- GATv2: 4 nodes/block, 64 threads (float4) per node -----------------------------
__global__ void __launch_bounds__(256) k_gat(const int* __restrict__ ei, const float* __restrict__ ea,
                                             const float* __restrict__ We, const float* __restrict__ att,
                                             const float* __restrict__ bias_gat,
                                             const float* __restrict__ g1, const float* __restrict__ be1)
{
    int q = threadIdx.x >> 6;
    int t = threadIdx.x & 63;
    int i = blockIdx.x * 4 + q;
    int c4 = t * 4;
    int hq = t >> 3;
    int wrp = threadIdx.x >> 5;

    __shared__ int   s_src[4][CAP];
    __shared__ float s_e0[4][CAP], s_e1[4][CAP];
    __shared__ float s_sc[4][(CAP + 1) * HEADS];
    __shared__ float s_Z[4][HEADS];
    __shared__ float s_r1[8], s_r2[8];

    int degr = g_deg[i];
    int deg  = degr > CAP ? CAP : degr;
    int off  = g_off[i];
    for (int k = t; k < deg; k += 64) {
        int eid = g_csr[off + k];
        s_src[q][k] = ei[eid];
        float2 e2 = *(const float2*)&ea[2*eid];
        s_e0[q][k] = e2.x;
        s_e1[q][k] = e2.y;
    }
    float4 xr4  = *(const float4*)&g_xr[(size_t)i*HD + c4];
    float4 xl4i = *(const float4*)&g_xl[(size_t)i*HD + c4];
    float4 we04 = *(const float4*)&We[c4];
    float4 we14 = *(const float4*)&We[HD + c4];
    float4 at4  = *(const float4*)&att[c4];
    float dr = fmaxf((float)degr, 1.0f);
    float m0 = g_easum[2*i] / dr, m1 = g_easum[2*i + 1] / dr;
    __syncthreads();

    for (int k = 0; k <= deg; k++) {
        float4 xls; float e0, e1;
        if (k < deg) {
            int s = s_src[q][k];
            xls = *(const float4*)&g_xl[(size_t)s*HD + c4];
            e0 = s_e0[q][k]; e1 = s_e1[q][k];
        } else { xls = xl4i; e0 = m0; e1 = m1; }
        float v0 = xls.x + xr4.x + e0*we04.x + e1*we14.x;
        float v1 = xls.y + xr4.y + e0*we04.y + e1*we14.y;
        float v2 = xls.z + xr4.z + e0*we04.z + e1*we14.z;
        float v3 = xls.w + xr4.w + e0*we04.w + e1*we14.w;
        v0 = v0 > 0.f ? v0 : 0.2f*v0;
        v1 = v1 > 0.f ? v1 : 0.2f*v1;
        v2 = v2 > 0.f ? v2 : 0.2f*v2;
        v3 = v3 > 0.f ? v3 : 0.2f*v3;
        float p = v0*at4.x + v1*at4.y + v2*at4.z + v3*at4.w;
        p += __shfl_xor_sync(0xffffffffu, p, 1);
        p += __shfl_xor_sync(0xffffffffu, p, 2);
        p += __shfl_xor_sync(0xffffffffu, p, 4);
        if ((t & 7) == 0) s_sc[q][k*HEADS + hq] = p;
    }
    __syncthreads();

    if (t < HEADS) {
        float m = -1e30f;
        for (int k = 0; k <= deg; k++) m = fmaxf(m, s_sc[q][k*HEADS + t]);
        float Z = 0.f;
        for (int k = 0; k <= deg; k++) { float e = __expf(s_sc[q][k*HEADS + t] - m); s_sc[q][k*HEADS + t] = e; Z += e; }
        s_Z[q][t] = Z;
    }
    __syncthreads();

    float a0 = 0.f, a1 = 0.f, a2 = 0.f, a3 = 0.f;
    for (int k = 0; k < deg; k++) {
        int s = s_src[q][k];
        float wgt = s_sc[q][k*HEADS + hq];
        float4 xls = *(const float4*)&g_xl[(size_t)s*HD + c4];
        a0 += wgt*xls.x; a1 += wgt*xls.y; a2 += wgt*xls.z; a3 += wgt*xls.w;
    }
    {
        float wgt = s_sc[q][deg*HEADS + hq];
        a0 += wgt*xl4i.x; a1 += wgt*xl4i.y; a2 += wgt*xl4i.z; a3 += wgt*xl4i.w;
    }
    float invZ = 1.0f / s_Z[q][hq];
    float4 bi4 = *(const float4*)&bias_gat[c4];
    float v0 = a0*invZ + bi4.x, v1 = a1*invZ + bi4.y;
    float v2 = a2*invZ + bi4.z, v3 = a3*invZ + bi4.w;

    float psum = warpsum(v0 + v1 + v2 + v3);
    if ((threadIdx.x & 31) == 0) s_r1[wrp] = psum;
    __syncthreads();
    float mean = (s_r1[2*q] + s_r1[2*q+1]) * (1.0f / 256.0f);
    float d0 = v0 - mean, d1 = v1 - mean, d2 = v2 - mean, d3 = v3 - mean;
    float pvar = warpsum(d0*d0 + d1*d1 + d2*d2 + d3*d3);
    if ((threadIdx.x & 31) == 0) s_r2[wrp] = pvar;
    __syncthreads();
    float var = (s_r2[2*q] + s_r2[2*q+1]) * (1.0f / 256.0f);
    float r = rsqrtf(var + 1e-5f);
    float4 gg = *(const float4*)&g1[c4];
    float4 bb = *(const float4*)&be1[c4];
    float4 o = { d0*r*gg.x + bb.x, d1*r*gg.y + bb.y, d2*r*gg.z + bb.z, d3*r*gg.w + bb.w };
    *(float4*)&g_local[(size_t)i*HD + c4] = o;
}

// ----------------------------- TF32 GEMM: perm layouts, cp.async 3-stage, chunk 32 -----------------------------
__global__ void __launch_bounds__(256, 2) k_gemm_p(const float* __restrict__ A, const float* __restrict__ B,
                                                   const float* __restrict__ bias, float* __restrict__ C,
                                                   int M, int N, int K, int act, int rnd, int permout)
{
    constexpr int ST = 8192;
    extern __shared__ unsigned sm[];
    unsigned smbase = (unsigned)__cvta_generic_to_shared(sm);

    int bm = blockIdx.y * 128, bn = blockIdx.x * 128;
    int tid = threadIdx.x;
    int wid = tid >> 5, lane = tid & 31;
    int warpm = wid >> 2, warpn = wid & 3;
    int lr = lane >> 2, lc = lane & 3;
    int K8 = K >> 3;

    float acc[4][4][4];
    #pragma unroll
    for (int mt = 0; mt < 4; mt++)
        #pragma unroll
        for (int nt = 0; nt < 4; nt++)
            #pragma unroll
            for (int q = 0; q < 4; q++) acc[mt][nt][q] = 0.f;

    int n32 = K >> 5;

    auto issue = [&](int ch){
        int st = ch % 3;
        int ko0 = ch << 2;
        unsigned ab = smbase + (unsigned)(st * ST) * 4u;
        unsigned bb = ab + 4096u * 4u;
        #pragma unroll
        for (int t = 0; t < 4; t++) {
            int wb = (tid + t*256) * 4;
            int mt8 = wb >> 9, ko = (wb >> 7) & 3, off = wb & 127;
            cpa16(ab + (unsigned)wb*4u,
                  &A[((size_t)((bm >> 4) + mt8) * K8 + ko0 + ko) * 128 + off]);
        }
        #pragma unroll
        for (int t = 0; t < 4; t++) {
            int wb = (tid + t*256) * 4;
            int nt16 = wb >> 8, ko = (wb >> 6) & 3, off = wb & 63;
            cpa16(bb + (unsigned)wb*4u,
                  &B[((size_t)((bn >> 3) + nt16) * K8 + ko0 + ko) * 64 + off]);
        }
        asm volatile("cp.async.commit_group;");
    };

    issue(0);
    issue(1);

    for (int ch = 0; ch < n32; ch++) {
        if (ch + 2 < n32) {
            asm volatile("cp.async.wait_group 1;");
            __syncthreads();
            issue(ch + 2);
        } else if (ch + 1 < n32) {
            asm volatile("cp.async.wait_group 1;");
            __syncthreads();
        } else {
            asm volatile("cp.async.wait_group 0;");
            __syncthreads();
        }

        int st = ch % 3;
        const unsigned* As = sm + st * ST;
        const unsigned* Bs = As + 4096;

        #pragma unroll
        for (int ko = 0; ko < 4; ko++) {
            unsigned af[4][4], bf[4][2];
            #pragma unroll
            for (int mt = 0; mt < 4; mt++) {
                uint4 v = *(const uint4*)&As[(((warpm*4 + mt)*4) + ko)*128 + lane*4];
                af[mt][0] = v.x; af[mt][1] = v.y; af[mt][2] = v.z; af[mt][3] = v.w;
            }
            #pragma unroll
            for (int nt = 0; nt < 4; nt++) {
                uint2 v = *(const uint2*)&Bs[(((warpn*4 + nt)*4) + ko)*64 + lane*2];
                bf[nt][0] = v.x; bf[nt][1] = v.y;
            }
            #pragma unroll
            for (int mt = 0; mt < 4; mt++)
                #pragma unroll
                for (int nt = 0; nt < 4; nt++)
                    mma_tf32(acc[mt][nt], af[mt], bf[nt][0], bf[nt][1]);
        }
    }

    #pragma unroll
    for (int mt = 0; mt < 4; mt++) {
        int r0 = bm + warpm*64 + mt*16 + lr;
        #pragma unroll
        for (int nt = 0; nt < 4; nt++) {
            int c0 = bn + warpn*32 + nt*8 + lc*2;
            float b0 = bias[c0], b1 = bias[c0+1];
            float v0 = acc[mt][nt][0] + b0, v1 = acc[mt][nt][1] + b1;
            float v2 = acc[mt][nt][2] + b0, v3 = acc[mt][nt][3] + b1;
            if (act) { v0 = geluf(v0); v1 = geluf(v1); v2 = geluf(v2); v3 = geluf(v3); }
            if (rnd) { v0 = tf32round(v0); v1 = tf32round(v1); v2 = tf32round(v2); v3 = tf32round(v3); }
            if (!permout) {
                float2 o0 = { v0, v1 }, o1 = { v2, v3 };
                *(float2*)&C[(size_t)r0*N + c0]       = o0;
                *(float2*)&C[(size_t)(r0+8)*N + c0]   = o1;
            } else {
                size_t w = aperm(r0, c0, N);
                float2 p0 = { v0, v2 }, p1 = { v1, v3 };
                *(float2*)&C[w]     = p0;
                *(float2*)&C[w + 4] = p1;
            }
        }
    }
}
#define GEMM_SMEM (8192 * 4 * 3)

// ----------------------------- TF32 flash attention: 512 threads, B-perm K/V + A-perm P -----------------------------
// smem: Ks B-perm 16384 | Vt B-perm 16384 | Ps 16*1024 = 49152 words = 192 KB
#define ATTN_SMEM_BYTES ((16384 + 16384 + 16384) * 4)
__global__ void __launch_bounds__(512, 1) k_attn()
{
    extern __shared__ unsigned smu[];
    unsigned* Ks = smu;
    unsigned* Vt = smu + 16384;
    unsigned* Ps = smu + 32768;

    int blk = blockIdx.x;
    int gh = blk >> 1, half = blk & 1;
    int g = gh >> 3, h = gh & 7;
    int tid = threadIdx.x, w = tid >> 5, lane = tid & 31;
    int lr = lane >> 2, lc = lane & 3;
    int gbase = g * NPG;
    const float SCALE = 0.17677669529663687f;

    // prologue: K and V into B-perm fragment layouts (raw bits)
    for (int idx = tid; idx < NPG * (CDIM/4); idx += 512) {
        int row = idx >> 3, c4 = idx & 7;
        size_t rb = (size_t)(gbase + row) * 768 + h*32 + c4*4;
        uint4 kv = *(const uint4*)&g_qkv[rb + 256];
        int kb = ((row >> 3) * 4 + (c4 >> 1)) * 64;
        int kw = ((row & 7) * 4) * 2 + (c4 & 1);
        Ks[kb + kw + 0] = kv.x;
        Ks[kb + kw + 2] = kv.y;
        Ks[kb + kw + 4] = kv.z;
        Ks[kb + kw + 6] = kv.w;
        uint4 vv = *(const uint4*)&g_qkv[rb + 512];
        int vb = ((c4 >> 1) * 64 + (row >> 3)) * 64;
        int vw = (((c4 & 1) * 4) * 4 + (row & 3)) * 2 + ((row >> 2) & 1);
        Vt[vb + vw +  0] = vv.x;
        Vt[vb + vw +  8] = vv.y;
        Vt[vb + vw + 16] = vv.z;
        Vt[vb + vw + 24] = vv.w;
    }
    __syncthreads();

    int qrow0 = half*256 + w*16;
    unsigned* Pw = Ps + w*1024;

    unsigned aq[4][4];
    {
        size_t r0 = (size_t)(gbase + qrow0 + lr)*768 + h*32;
        size_t r1 = (size_t)(gbase + qrow0 + lr + 8)*768 + h*32;
        #pragma unroll
        for (int s = 0; s < 4; s++) {
            aq[s][0] = __float_as_uint(g_qkv[r0 + s*8 + lc]);
            aq[s][1] = __float_as_uint(g_qkv[r1 + s*8 + lc]);
            aq[s][2] = __float_as_uint(g_qkv[r0 + s*8 + 4 + lc]);
            aq[s][3] = __float_as_uint(g_qkv[r1 + s*8 + 4 + lc]);
        }
    }

    float m0 = -1e30f, m1 = -1e30f, l0 = 0.f, l1 = 0.f;
    float oacc[4][4];
    #pragma unroll
    for (int nt = 0; nt < 4; nt++)
        #pragma unroll
        for (int q = 0; q < 4; q++) oacc[nt][q] = 0.f;

    int wbase = (4*lr + ((2*lc) & 3))*4 + ((lc >> 1) << 1);

    for (int j = 0; j < 4; j++) {
        int jb = j*128;
        float sacc[16][4];
        #pragma unroll
        for (int nt = 0; nt < 16; nt++)
            #pragma unroll
            for (int q = 0; q < 4; q++) sacc[nt][q] = 0.f;

        #pragma unroll
        for (int nt = 0; nt < 16; nt++) {
            int kb = ((jb >> 3) + nt) * 4;
            #pragma unroll
            for (int s = 0; s < 4; s++) {
                uint2 bv = *(const uint2*)&Ks[(kb + s)*64 + lane*2];
                mma_tf32(sacc[nt], aq[s], bv.x, bv.y);
            }
        }

        float cm0 = -1e30f, cm1 = -1e30f;
        #pragma unroll
        for (int nt = 0; nt < 16; nt++) {
            cm0 = fmaxf(cm0, fmaxf(sacc[nt][0], sacc[nt][1]));
            cm1 = fmaxf(cm1, fmaxf(sacc[nt][2], sacc[nt][3]));
        }
        cm0 = fmaxf(cm0, __shfl_xor_sync(0xffffffffu, cm0, 1));
        cm0 = fmaxf(cm0, __shfl_xor_sync(0xffffffffu, cm0, 2));
        cm1 = fmaxf(cm1, __shfl_xor_sync(0xffffffffu, cm1, 1));
        cm1 = fmaxf(cm1, __shfl_xor_sync(0xffffffffu, cm1, 2));

        float nm0 = fmaxf(m0, cm0), nm1 = fmaxf(m1, cm1);
        float sc0 = __expf((m0 - nm0) * SCALE), sc1 = __expf((m1 - nm1) * SCALE);
        m0 = nm0; m1 = nm1;
        #pragma unroll
        for (int nt = 0; nt < 4; nt++) {
            oacc[nt][0] *= sc0; oacc[nt][1] *= sc0;
            oacc[nt][2] *= sc1; oacc[nt][3] *= sc1;
        }

        float ps0 = 0.f, ps1 = 0.f;
        #pragma unroll
        for (int htg = 0; htg < 2; htg++) {
            #pragma unroll
            for (int ntl = 0; ntl < 8; ntl++) {
                int nt = htg*8 + ntl;
                float p0 = __expf((sacc[nt][0] - nm0) * SCALE);
                float p1 = __expf((sacc[nt][1] - nm0) * SCALE);
                float p2 = __expf((sacc[nt][2] - nm1) * SCALE);
                float p3 = __expf((sacc[nt][3] - nm1) * SCALE);
                ps0 += p0 + p1; ps1 += p2 + p3;
                int W = ntl*128 + wbase;
                uint2 q0 = { __float_as_uint(p0), __float_as_uint(p2) };
                uint2 q1 = { __float_as_uint(p1), __float_as_uint(p3) };
                *(uint2*)&Pw[W]     = q0;
                *(uint2*)&Pw[W + 4] = q1;
            }
            __syncwarp();
            #pragma unroll
            for (int s2 = 0; s2 < 8; s2++) {
                uint4 av = *(const uint4*)&Pw[s2*128 + lane*4];
                unsigned ap[4] = { av.x, av.y, av.z, av.w };
                int kblk = (jb + htg*64 + s2*8) >> 3;
                #pragma unroll
                for (int nt2 = 0; nt2 < 4; nt2++) {
                    uint2 bv = *(const uint2*)&Vt[(nt2*64 + kblk)*64 + lane*2];
                    mma_tf32(oacc[nt2], ap, bv.x, bv.y);
                }
            }
            __syncwarp();
        }
        ps0 += __shfl_xor_sync(0xffffffffu, ps0, 1);
        ps0 += __shfl_xor_sync(0xffffffffu, ps0, 2);
        ps1 += __shfl_xor_sync(0xffffffffu, ps1, 1);
        ps1 += __shfl_xor_sync(0xffffffffu, ps1, 2);
        l0 = l0 * sc0 + ps0;
        l1 = l1 * sc1 + ps1;
    }

    float inv0 = 1.0f / l0, inv1 = 1.0f / l1;
    int row0 = gbase + qrow0 + lr;
    #pragma unroll
    for (int nt2 = 0; nt2 < 4; nt2++) {
        int col = h*32 + nt2*8 + 2*lc;
        size_t wd = aperm(row0, col, HD);
        float2 p0 = { tf32round(oacc[nt2][0]*inv0), tf32round(oacc[nt2][2]*inv1) };
        float2 p1 = { tf32round(oacc[nt2][1]*inv0), tf32round(oacc[nt2][3]*inv1) };
        *(float2*)&g_attno[wd]     = p0;
        *(float2*)&g_attno[wd + 4] = p1;
    }
}

// ----------------------------- LN2 + combine (comb written A-perm) -----------------------------
__global__ void __launch_bounds__(256) k_combine(const float* __restrict__ g2, const float* __restrict__ be2,
                                                 const float* __restrict__ alpha_p)
{
    int w = threadIdx.x >> 5, lane = threadIdx.x & 31;
    int row = blockIdx.x * 8 + w;
    const float4* gr = (const float4*)&g_graw[(size_t)row*HD + lane*8];
    float4 a0 = gr[0], a1 = gr[1];
    float s = a0.x+a0.y+a0.z+a0.w + a1.x+a1.y+a1.z+a1.w;
    float mean = warpsum(s) * (1.0f/256.0f);
    float d[8] = { a0.x-mean, a0.y-mean, a0.z-mean, a0.w-mean,
                   a1.x-mean, a1.y-mean, a1.z-mean, a1.w-mean };
    float vs = 0.f;
    #pragma unroll
    for (int t = 0; t < 8; t++) vs += d[t]*d[t];
    float r = rsqrtf(warpsum(vs) * (1.0f/256.0f) + 1e-5f);
    float a = 1.0f / (1.0f + __expf(-alpha_p[0]));
    float oma = 1.0f - a;
    const float4* G2 = (const float4*)&g2[lane*8];
    const float4* B2 = (const float4*)&be2[lane*8];
    float4 gg0 = G2[0], gg1 = G2[1], bb0 = B2[0], bb1 = B2[1];
    const float4* loc = (const float4*)&g_local[(size_t)row*HD + lane*8];
    float4 l0 = loc[0], l1 = loc[1];
    float ov[8];
    ov[0] = a*l0.x + oma*(d[0]*r*gg0.x + bb0.x);
    ov[1] = a*l0.y + oma*(d[1]*r*gg0.y + bb0.y);
    ov[2] = a*l0.z + oma*(d[2]*r*gg0.z + bb0.z);
    ov[3] = a*l0.w + oma*(d[3]*r*gg0.w + bb0.w);
    ov[4] = a*l1.x + oma*(d[4]*r*gg1.x + bb1.x);
    ov[5] = a*l1.y + oma*(d[5]*r*gg1.y + bb1.y);
    ov[6] = a*l1.z + oma*(d[6]*r*gg1.z + bb1.z);
    ov[7] = a*l1.w + oma*(d[7]*r*gg1.w + bb1.w);
    size_t base = (size_t)((row >> 4) * 32 + lane) * 128;
    int rb = ((row & 7) * 4) * 4 + ((row >> 3) & 1);
    #pragma unroll
    for (int t = 0; t < 8; t++)
        g_comb[base + rb + (t & 3)*4 + ((t >> 2) << 1)] = tf32round(ov[t]);
}

// ----------------------------- residual + LN3 -> out (reads comb A-perm) -----------------------------
__global__ void __launch_bounds__(256) k_final(const float* __restrict__ g3, const float* __restrict__ be3,
                                               float* __restrict__ out)
{
    int w = threadIdx.x >> 5, lane = threadIdx.x & 31;
    int row = blockIdx.x * 8 + w;
    size_t base = (size_t)((row >> 4) * 32 + lane) * 128;
    int rb = ((row & 7) * 4) * 4 + ((row >> 3) & 1);
    float cv[8];
    #pragma unroll
    for (int t = 0; t < 8; t++)
        cv[t] = g_comb[base + rb + (t & 3)*4 + ((t >> 2) << 1)];
    const float4* f2 = (const float4*)&g_f2[(size_t)row*HD + lane*8];
    float4 e0 = f2[0], e1 = f2[1];
    float v[8] = { cv[0]+e0.x, cv[1]+e0.y, cv[2]+e0.z, cv[3]+e0.w,
                   cv[4]+e1.x, cv[5]+e1.y, cv[6]+e1.z, cv[7]+e1.w };
    float s = 0.f;
    #pragma unroll
    for (int t = 0; t < 8; t++) s += v[t];
    float mean = warpsum(s) * (1.0f/256.0f);
    float vs = 0.f;
    #pragma unroll
    for (int t = 0; t < 8; t++) { v[t] -= mean; vs += v[t]*v[t]; }
    float r = rsqrtf(warpsum(vs) * (1.0f/256.0f) + 1e-5f);
    const float4* G3 = (const float4*)&g3[lane*8];
    const float4* B3 = (const float4*)&be3[lane*8];
    float4 gg0 = G3[0], gg1 = G3[1], bb0 = B3[0], bb1 = B3[1];
    float4 o0, o1;
    o0.x = v[0]*r*gg0.x + bb0.x; o0.y = v[1]*r*gg0.y + bb0.y;
    o0.z = v[2]*r*gg0.z + bb0.z; o0.w = v[3]*r*gg0.w + bb0.w;
    o1.x = v[4]*r*gg1.x + bb1.x; o1.y = v[5]*r*gg1.y + bb1.y;
    o1.z = v[6]*r*gg1.z + bb1.z; o1.w = v[7]*r*gg1.w + bb1.w;
    float4* dst = (float4*)&out[(size_t)row*HD + lane*8];
    dst[0] = o0; dst[1] = o1;
}

// ----------------------------- launch -----------------------------
extern "C" void kernel_launch(void* const* d_in, const int* in_sizes, int n_in,
                              void* d_out, int out_size)
{
    const float* x        = (const float*)d_in[0];
    const float* ea       = (const float*)d_in[1];
    const float* W_l      = (const float*)d_in[2];
    const float* b_l      = (const float*)d_in[3];
    const float* W_r      = (const float*)d_in[4];
    const float* b_r      = (const float*)d_in[5];
    const float* W_e      = (const float*)d_in[6];
    const float* att      = (const float*)d_in[7];
    const float* bias_gat = (const float*)d_in[8];
    const float* ipw      = (const float*)d_in[9];
    const float* ipb      = (const float*)d_in[10];
    const float* opw      = (const float*)d_in[11];
    const float* opb      = (const float*)d_in[12];
    const float* alpha    = (const float*)d_in[13];
    const float* W1       = (const float*)d_in[14];
    const float* b1       = (const float*)d_in[15];
    const float* W2       = (const float*)d_in[16];
    const float* b2       = (const float*)d_in[17];
    const float* g1       = (const float*)d_in[18];
    const float* be1      = (const float*)d_in[19];
    const float* g2       = (const float*)d_in[20];
    const float* be2      = (const float*)d_in[21];
    const float* g3       = (const float*)d_in[22];
    const float* be3      = (const float*)d_in[23];
    const int*   ei       = (const int*)d_in[24];
    float* out = (float*)d_out;

    float *xl, *xr, *qkv, *attno, *graw, *comb, *h1, *f2;
    float *rx, *rwl, *rwr, *ripw, *ropw, *rw1, *rw2;
    cudaGetSymbolAddress((void**)&xl,    g_xl);
    cudaGetSymbolAddress((void**)&xr,    g_xr);
    cudaGetSymbolAddress((void**)&qkv,   g_qkv);
    cudaGetSymbolAddress((void**)&attno, g_attno);
    cudaGetSymbolAddress((void**)&graw,  g_graw);
    cudaGetSymbolAddress((void**)&comb,  g_comb);
    cudaGetSymbolAddress((void**)&h1,    g_h1);
    cudaGetSymbolAddress((void**)&f2,    g_f2);
    cudaGetSymbolAddress((void**)&rx,    g_rx);
    cudaGetSymbolAddress((void**)&rwl,   g_rwl);
    cudaGetSymbolAddress((void**)&rwr,   g_rwr);
    cudaGetSymbolAddress((void**)&ripw,  g_ripw);
    cudaGetSymbolAddress((void**)&ropw,  g_ropw);
    cudaGetSymbolAddress((void**)&rw1,   g_rw1);
    cudaGetSymbolAddress((void**)&rw2,   g_rw2);

    cudaFuncSetAttribute(k_attn,   cudaFuncAttributeMaxDynamicSharedMemorySize, ATTN_SMEM_BYTES);
    cudaFuncSetAttribute(k_gemm_p, cudaFuncAttributeMaxDynamicSharedMemorySize, GEMM_SMEM);

    // attention path first: launch index 3 = k_attn (profiled)
    k_repa<<<(NTOT*HD/4 + 255)/256, 256>>>(x, rx, NTOT, HD);                          // 0
    k_repb<true><<<(3*HD*HD/2 + 255)/256, 256>>>(ipw, ripw, 3*HD, HD);                // 1
    k_gemm_p<<<dim3(3*HD/128, NTOT/128), 256, GEMM_SMEM>>>(rx, ripw, ipb, qkv, NTOT, 3*HD, HD, 0, 0, 0);  // 2
    k_attn<<<GRAPHS*HEADS*2, 512, ATTN_SMEM_BYTES>>>();                               // 3 <- profiled
    k_repb<true><<<(HD*HD/2 + 255)/256, 256>>>(opw, ropw, HD, HD);
    k_gemm_p<<<dim3(HD/128, NTOT/128), 256, GEMM_SMEM>>>(attno, ropw, opb, graw, NTOT, HD, HD, 0, 0, 0);

    // GAT path
    k_repb<false><<<(HD*HD/2 + 255)/256, 256>>>(W_l, rwl, HD, HD);
    k_repb<false><<<(HD*HD/2 + 255)/256, 256>>>(W_r, rwr, HD, HD);
    k_gemm_p<<<dim3(HD/128, NTOT/128), 256, GEMM_SMEM>>>(rx, rwl, b_l, xl, NTOT, HD, HD, 0, 0, 0);
    k_gemm_p<<<dim3(HD/128, NTOT/128), 256, GEMM_SMEM>>>(rx, rwr, b_r, xr, NTOT, HD, HD, 0, 0, 0);
    k_zero<<<(NTOT + 255)/256, 256>>>();
    k_edgecnt<<<(EDG + 255)/256, 256>>>(ei, ea);
    k_scan<<<1, 1024>>>();
    k_fill<<<(EDG + 255)/256, 256>>>(ei);
    k_gat<<<NTOT/4, 256>>>(ei, ea, W_e, att, bias_gat, g1, be1);

    // combine + FFN + final LN
    k_combine<<<NTOT/8, 256>>>(g2, be2, alpha);
    k_repb<false><<<(HD*4*HD/2 + 255)/256, 256>>>(W1, rw1, 4*HD, HD);
    k_repb<false><<<(4*HD*HD/2 + 255)/256, 256>>>(W2, rw2, HD, 4*HD);
    k_gemm_p<<<dim3(4*HD/128, NTOT/128), 256, GEMM_SMEM>>>(comb, rw1, b1, h1, NTOT, 4*HD, HD, 1, 1, 1);
    k_gemm_p<<<dim3(HD/128, NTOT/128), 256, GEMM_SMEM>>>(h1, rw2, b2, f2, NTOT, HD, 4*HD, 0, 0, 0);
    k_final<<<NTOT/8, 256>>>(g3, be3, out);

    (void)in_sizes; (void)n_in; (void)out_size;
}

// round 17
// speedup vs baseline: 1.0198x; 1.0198x over previous
#include <cuda_runtime.h>
#include <math.h>

#define NTOT   32768
#define EDG    524288
#define HD     256
#define HEADS  8
#define CDIM   32
#define GRAPHS 64
#define NPG    512
#define CAP    128
#define NBIG   1280   // fused out width: qkv(768) | xl(256) | xr(256)

// ----------------------------- scratch (static device) -----------------------------
__device__ __align__(16) float g_big[NTOT*NBIG];   // qkv | xl | xr
__device__ __align__(16) float g_attno[NTOT*HD];   // A-perm
__device__ __align__(16) float g_graw[NTOT*HD];
__device__ __align__(16) float g_local[NTOT*HD];
__device__ __align__(16) float g_comb[NTOT*HD];    // A-perm
__device__ __align__(16) float g_h1[NTOT*4*HD];    // A-perm
__device__ __align__(16) float g_f2[NTOT*HD];
__device__ __align__(16) float g_rx[NTOT*HD];      // A-perm
__device__ __align__(16) float g_rbig[NBIG*HD];    // B-perm fused weights
__device__ __align__(16) float g_ropw[HD*HD];
__device__ __align__(16) float g_rw1[HD*4*HD];
__device__ __align__(16) float g_rw2[4*HD*HD];
__device__ float g_bias[NBIG];
__device__ int   g_deg[NTOT];
__device__ int   g_off[NTOT];
__device__ int   g_cur[NTOT];
__device__ int   g_csr[EDG];
__device__ float g_easum[NTOT*2];

// ----------------------------- helpers -----------------------------
__device__ __forceinline__ unsigned tf32cvt(float f){
    unsigned r;
    asm("cvt.rna.tf32.f32 %0,%1;" : "=r"(r) : "f"(f));
    return r;
}
__device__ __forceinline__ float tf32round(float f){
    return __uint_as_float(tf32cvt(f));
}
__device__ __forceinline__ void mma_tf32(float* c, const unsigned* a, unsigned b0, unsigned b1){
    asm volatile(
        "mma.sync.aligned.m16n8k8.row.col.f32.tf32.tf32.f32 "
        "{%0,%1,%2,%3},{%4,%5,%6,%7},{%8,%9},{%0,%1,%2,%3};"
        : "+f"(c[0]), "+f"(c[1]), "+f"(c[2]), "+f"(c[3])
        : "r"(a[0]), "r"(a[1]), "r"(a[2]), "r"(a[3]), "r"(b0), "r"(b1));
}
__device__ __forceinline__ void cpa16(unsigned dst, const void* src){
    asm volatile("cp.async.cg.shared.global [%0], [%1], 16;" :: "r"(dst), "l"(src));
}
__device__ __forceinline__ float geluf(float x){
    return 0.5f * x * (1.0f + erff(x * 0.70710678118654752f));
}
__device__ __forceinline__ size_t aperm(int m, int k, int K){
    return (size_t)((m >> 4) * (K >> 3) + (k >> 3)) * 128
         + ((m & 7) * 4 + (k & 3)) * 4 + ((m >> 3) & 1) + (((k >> 2) & 1) << 1);
}
__device__ __forceinline__ float warpsum(float v){
    #pragma unroll
    for (int o = 16; o; o >>= 1) v += __shfl_xor_sync(0xffffffffu, v, o);
    return v;
}

// ----------------------------- init: graph counters + fused bias concat -----------------------------
__global__ void k_init(const float* __restrict__ ipb, const float* __restrict__ b_l,
                       const float* __restrict__ b_r){
    int i = blockIdx.x * blockDim.x + threadIdx.x;
    if (i < NTOT) { g_deg[i] = 0; g_cur[i] = 0; g_easum[2*i] = 0.f; g_easum[2*i+1] = 0.f; }
    if (i < NBIG) g_bias[i] = (i < 768) ? ipb[i] : ((i < 1024) ? b_l[i - 768] : b_r[i - 1024]);
}

// ----------------------------- repack kernels -----------------------------
__global__ void k_repa(const float* __restrict__ in, float* __restrict__ outp, int M, int K){
    int i = blockIdx.x * blockDim.x + threadIdx.x;
    if (i >= M * (K >> 2)) return;
    int m = i / (K >> 2), kq = i % (K >> 2);
    float4 v = ((const float4*)in)[(size_t)m * (K >> 2) + kq];
    size_t base = (size_t)((m >> 4) * (K >> 3) + (kq >> 1)) * 128
                + ((m & 7) * 4) * 4 + ((m >> 3) & 1) + ((kq & 1) << 1);
    outp[base +  0] = tf32round(v.x);
    outp[base +  4] = tf32round(v.y);
    outp[base +  8] = tf32round(v.z);
    outp[base + 12] = tf32round(v.w);
}
// B repack into B-perm at row offset n0 (multiple of 8) within a dest of K8 k-blocks.
template<bool SRC_TB>
__global__ void k_repb(const float* __restrict__ in, float* __restrict__ outp, int N, int K, int n0){
    int w2 = blockIdx.x * blockDim.x + threadIdx.x;
    if (w2 >= (N * K) >> 1) return;
    int K8 = K >> 3;
    int blk = w2 >> 5, pi = w2 & 31;
    int n7 = pi >> 2, k3 = pi & 3;
    int nb = blk / K8, k8 = blk % K8;
    int n = nb * 8 + n7;
    int ka = k8 * 8 + k3, kb = ka + 4;
    float va, vb;
    if (SRC_TB) { va = in[(size_t)n * K + ka]; vb = in[(size_t)n * K + kb]; }
    else        { va = in[(size_t)ka * N + n]; vb = in[(size_t)kb * N + n]; }
    float2 o = { tf32round(va), tf32round(vb) };
    *(float2*)&outp[((size_t)(((n0 >> 3) + nb) * K8 + k8)) * 64 + pi * 2] = o;
}

// ----------------------------- graph kernels -----------------------------
__global__ void k_edgecnt(const int* __restrict__ ei, const float* __restrict__ ea){
    int e = blockIdx.x * blockDim.x + threadIdx.x;
    if (e < EDG) {
        int d = ei[EDG + e];
        atomicAdd(&g_deg[d], 1);
        atomicAdd(&g_easum[2*d],     ea[2*e]);
        atomicAdd(&g_easum[2*d + 1], ea[2*e + 1]);
    }
}
__global__ void k_scan(){
    __shared__ int wsum[32];
    int tid = threadIdx.x;
    int base = tid * 32;
    int loc[32]; int s = 0;
    #pragma unroll
    for (int t = 0; t < 32; t++) { loc[t] = s; s += g_deg[base + t]; }
    int lane = tid & 31, wid = tid >> 5;
    int v = s;
    #pragma unroll
    for (int o = 1; o < 32; o <<= 1) { int n = __shfl_up_sync(0xffffffffu, v, o); if (lane >= o) v += n; }
    if (lane == 31) wsum[wid] = v;
    __syncthreads();
    if (wid == 0) {
        int w = wsum[lane];
        #pragma unroll
        for (int o = 1; o < 32; o <<= 1) { int n = __shfl_up_sync(0xffffffffu, w, o); if (lane >= o) w += n; }
        wsum[lane] = w;
    }
    __syncthreads();
    int chunk_base = v - s + (wid ? wsum[wid - 1] : 0);
    #pragma unroll
    for (int t = 0; t < 32; t++) g_off[base + t] = chunk_base + loc[t];
}
__global__ void k_fill(const int* __restrict__ ei){
    int e = blockIdx.x * blockDim.x + threadIdx.x;
    if (e < EDG) {
        int d = ei[EDG + e];
        int p = atomicAdd(&g_cur[d], 1);
        g_csr[g_off[d] + p] = e;
    }
}

// ----------------------------- GATv2: 4 nodes/block; xl/xr live in g_big cols 768+/1024+ -----------------------------
__global__ void __launch_bounds__(256) k_gat(const int* __restrict__ ei, const float* __restrict__ ea,
                                             const float* __restrict__ We, const float* __restrict__ att,
                                             const float* __restrict__ bias_gat,
                                             const float* __restrict__ g1, const float* __restrict__ be1)
{
    int q = threadIdx.x >> 6;
    int t = threadIdx.x & 63;
    int i = blockIdx.x * 4 + q;
    int c4 = t * 4;
    int hq = t >> 3;
    int wrp = threadIdx.x >> 5;

    __shared__ int   s_src[4][CAP];
    __shared__ float s_e0[4][CAP], s_e1[4][CAP];
    __shared__ float s_sc[4][(CAP + 1) * HEADS];
    __shared__ float s_Z[4][HEADS];
    __shared__ float s_r1[8], s_r2[8];

    int degr = g_deg[i];
    int deg  = degr > CAP ? CAP : degr;
    int off  = g_off[i];
    for (int k = t; k < deg; k += 64) {
        int eid = g_csr[off + k];
        s_src[q][k] = ei[eid];
        float2 e2 = *(const float2*)&ea[2*eid];
        s_e0[q][k] = e2.x;
        s_e1[q][k] = e2.y;
    }
    float4 xr4  = *(const float4*)&g_big[(size_t)i*NBIG + 1024 + c4];
    float4 xl4i = *(const float4*)&g_big[(size_t)i*NBIG + 768 + c4];
    float4 we04 = *(const float4*)&We[c4];
    float4 we14 = *(const float4*)&We[HD + c4];
    float4 at4  = *(const float4*)&att[c4];
    float dr = fmaxf((float)degr, 1.0f);
    float m0 = g_easum[2*i] / dr, m1 = g_easum[2*i + 1] / dr;
    __syncthreads();

    for (int k = 0; k <= deg; k++) {
        float4 xls; float e0, e1;
        if (k < deg) {
            int s = s_src[q][k];
            xls = *(const float4*)&g_big[(size_t)s*NBIG + 768 + c4];
            e0 = s_e0[q][k]; e1 = s_e1[q][k];
        } else { xls = xl4i; e0 = m0; e1 = m1; }
        float v0 = xls.x + xr4.x + e0*we04.x + e1*we14.x;
        float v1 = xls.y + xr4.y + e0*we04.y + e1*we14.y;
        float v2 = xls.z + xr4.z + e0*we04.z + e1*we14.z;
        float v3 = xls.w + xr4.w + e0*we04.w + e1*we14.w;
        v0 = v0 > 0.f ? v0 : 0.2f*v0;
        v1 = v1 > 0.f ? v1 : 0.2f*v1;
        v2 = v2 > 0.f ? v2 : 0.2f*v2;
        v3 = v3 > 0.f ? v3 : 0.2f*v3;
        float p = v0*at4.x + v1*at4.y + v2*at4.z + v3*at4.w;
        p += __shfl_xor_sync(0xffffffffu, p, 1);
        p += __shfl_xor_sync(0xffffffffu, p, 2);
        p += __shfl_xor_sync(0xffffffffu, p, 4);
        if ((t & 7) == 0) s_sc[q][k*HEADS + hq] = p;
    }
    __syncthreads();

    if (t < HEADS) {
        float m = -1e30f;
        for (int k = 0; k <= deg; k++) m = fmaxf(m, s_sc[q][k*HEADS + t]);
        float Z = 0.f;
        for (int k = 0; k <= deg; k++) { float e = __expf(s_sc[q][k*HEADS + t] - m); s_sc[q][k*HEADS + t] = e; Z += e; }
        s_Z[q][t] = Z;
    }
    __syncthreads();

    float a0 = 0.f, a1 = 0.f, a2 = 0.f, a3 = 0.f;
    for (int k = 0; k < deg; k++) {
        int s = s_src[q][k];
        float wgt = s_sc[q][k*HEADS + hq];
        float4 xls = *(const float4*)&g_big[(size_t)s*NBIG + 768 + c4];
        a0 += wgt*xls.x; a1 += wgt*xls.y; a2 += wgt*xls.z; a3 += wgt*xls.w;
    }
    {
        float wgt = s_sc[q][deg*HEADS + hq];
        a0 += wgt*xl4i.x; a1 += wgt*xl4i.y; a2 += wgt*xl4i.z; a3 += wgt*xl4i.w;
    }
    float invZ = 1.0f / s_Z[q][hq];
    float4 bi4 = *(const float4*)&bias_gat[c4];
    float v0 = a0*invZ + bi4.x, v1 = a1*invZ + bi4.y;
    float v2 = a2*invZ + bi4.z, v3 = a3*invZ + bi4.w;

    float psum = warpsum(v0 + v1 + v2 + v3);
    if ((threadIdx.x & 31) == 0) s_r1[wrp] = psum;
    __syncthreads();
    float mean = (s_r1[2*q] + s_r1[2*q+1]) * (1.0f / 256.0f);
    float d0 = v0 - mean, d1 = v1 - mean, d2 = v2 - mean, d3 = v3 - mean;
    float pvar = warpsum(d0*d0 + d1*d1 + d2*d2 + d3*d3);
    if ((threadIdx.x & 31) == 0) s_r2[wrp] = pvar;
    __syncthreads();
    float var = (s_r2[2*q] + s_r2[2*q+1]) * (1.0f / 256.0f);
    float r = rsqrtf(var + 1e-5f);
    float4 gg = *(const float4*)&g1[c4];
    float4 bb = *(const float4*)&be1[c4];
    float4 o = { d0*r*gg.x + bb.x, d1*r*gg.y + bb.y, d2*r*gg.z + bb.z, d3*r*gg.w + bb.w };
    *(float4*)&g_local[(size_t)i*HD + c4] = o;
}

// ----------------------------- TF32 GEMM: perm layouts, cp.async 3-stage, chunk 32 -----------------------------
__global__ void __launch_bounds__(256, 2) k_gemm_p(const float* __restrict__ A, const float* __restrict__ B,
                                                   const float* __restrict__ bias, float* __restrict__ C,
                                                   int M, int N, int K, int act, int rnd, int permout)
{
    constexpr int ST = 8192;
    extern __shared__ unsigned sm[];
    unsigned smbase = (unsigned)__cvta_generic_to_shared(sm);

    int bm = blockIdx.y * 128, bn = blockIdx.x * 128;
    int tid = threadIdx.x;
    int wid = tid >> 5, lane = tid & 31;
    int warpm = wid >> 2, warpn = wid & 3;
    int lr = lane >> 2, lc = lane & 3;
    int K8 = K >> 3;

    float acc[4][4][4];
    #pragma unroll
    for (int mt = 0; mt < 4; mt++)
        #pragma unroll
        for (int nt = 0; nt < 4; nt++)
            #pragma unroll
            for (int q = 0; q < 4; q++) acc[mt][nt][q] = 0.f;

    int n32 = K >> 5;

    auto issue = [&](int ch){
        int st = ch % 3;
        int ko0 = ch << 2;
        unsigned ab = smbase + (unsigned)(st * ST) * 4u;
        unsigned bb = ab + 4096u * 4u;
        #pragma unroll
        for (int t = 0; t < 4; t++) {
            int wb = (tid + t*256) * 4;
            int mt8 = wb >> 9, ko = (wb >> 7) & 3, off = wb & 127;
            cpa16(ab + (unsigned)wb*4u,
                  &A[((size_t)((bm >> 4) + mt8) * K8 + ko0 + ko) * 128 + off]);
        }
        #pragma unroll
        for (int t = 0; t < 4; t++) {
            int wb = (tid + t*256) * 4;
            int nt16 = wb >> 8, ko = (wb >> 6) & 3, off = wb & 63;
            cpa16(bb + (unsigned)wb*4u,
                  &B[((size_t)((bn >> 3) + nt16) * K8 + ko0 + ko) * 64 + off]);
        }
        asm volatile("cp.async.commit_group;");
    };

    issue(0);
    issue(1);

    for (int ch = 0; ch < n32; ch++) {
        if (ch + 2 < n32) {
            asm volatile("cp.async.wait_group 1;");
            __syncthreads();
            issue(ch + 2);
        } else if (ch + 1 < n32) {
            asm volatile("cp.async.wait_group 1;");
            __syncthreads();
        } else {
            asm volatile("cp.async.wait_group 0;");
            __syncthreads();
        }

        int st = ch % 3;
        const unsigned* As = sm + st * ST;
        const unsigned* Bs = As + 4096;

        #pragma unroll
        for (int ko = 0; ko < 4; ko++) {
            unsigned af[4][4], bf[4][2];
            #pragma unroll
            for (int mt = 0; mt < 4; mt++) {
                uint4 v = *(const uint4*)&As[(((warpm*4 + mt)*4) + ko)*128 + lane*4];
                af[mt][0] = v.x; af[mt][1] = v.y; af[mt][2] = v.z; af[mt][3] = v.w;
            }
            #pragma unroll
            for (int nt = 0; nt < 4; nt++) {
                uint2 v = *(const uint2*)&Bs[(((warpn*4 + nt)*4) + ko)*64 + lane*2];
                bf[nt][0] = v.x; bf[nt][1] = v.y;
            }
            #pragma unroll
            for (int mt = 0; mt < 4; mt++)
                #pragma unroll
                for (int nt = 0; nt < 4; nt++)
                    mma_tf32(acc[mt][nt], af[mt], bf[nt][0], bf[nt][1]);
        }
    }

    #pragma unroll
    for (int mt = 0; mt < 4; mt++) {
        int r0 = bm + warpm*64 + mt*16 + lr;
        #pragma unroll
        for (int nt = 0; nt < 4; nt++) {
            int c0 = bn + warpn*32 + nt*8 + lc*2;
            float b0 = bias[c0], b1 = bias[c0+1];
            float v0 = acc[mt][nt][0] + b0, v1 = acc[mt][nt][1] + b1;
            float v2 = acc[mt][nt][2] + b0, v3 = acc[mt][nt][3] + b1;
            if (act) { v0 = geluf(v0); v1 = geluf(v1); v2 = geluf(v2); v3 = geluf(v3); }
            if (rnd) { v0 = tf32round(v0); v1 = tf32round(v1); v2 = tf32round(v2); v3 = tf32round(v3); }
            if (!permout) {
                float2 o0 = { v0, v1 }, o1 = { v2, v3 };
                *(float2*)&C[(size_t)r0*N + c0]       = o0;
                *(float2*)&C[(size_t)(r0+8)*N + c0]   = o1;
            } else {
                size_t w = aperm(r0, c0, N);
                float2 p0 = { v0, v2 }, p1 = { v1, v3 };
                *(float2*)&C[w]     = p0;
                *(float2*)&C[w + 4] = p1;
            }
        }
    }
}
#define GEMM_SMEM (8192 * 4 * 3)

// ----------------------------- TF32 flash attention: 512 threads, B-perm K/V + A-perm P -----------------------------
#define ATTN_SMEM_BYTES ((16384 + 16384 + 16384) * 4)
__global__ void __launch_bounds__(512, 1) k_attn()
{
    extern __shared__ unsigned smu[];
    unsigned* Ks = smu;
    unsigned* Vt = smu + 16384;
    unsigned* Ps = smu + 32768;

    int blk = blockIdx.x;
    int gh = blk >> 1, half = blk & 1;
    int g = gh >> 3, h = gh & 7;
    int tid = threadIdx.x, w = tid >> 5, lane = tid & 31;
    int lr = lane >> 2, lc = lane & 3;
    int gbase = g * NPG;
    const float SCALE = 0.17677669529663687f;

    // prologue: K and V into B-perm fragment layouts (raw bits); qkv lives in g_big cols 0..767, stride NBIG
    for (int idx = tid; idx < NPG * (CDIM/4); idx += 512) {
        int row = idx >> 3, c4 = idx & 7;
        size_t rb = (size_t)(gbase + row) * NBIG + h*32 + c4*4;
        uint4 kv = *(const uint4*)&g_big[rb + 256];
        int kb = ((row >> 3) * 4 + (c4 >> 1)) * 64;
        int kw = ((row & 7) * 4) * 2 + (c4 & 1);
        Ks[kb + kw + 0] = kv.x;
        Ks[kb + kw + 2] = kv.y;
        Ks[kb + kw + 4] = kv.z;
        Ks[kb + kw + 6] = kv.w;
        uint4 vv = *(const uint4*)&g_big[rb + 512];
        int vb = ((c4 >> 1) * 64 + (row >> 3)) * 64;
        int vw = (((c4 & 1) * 4) * 4 + (row & 3)) * 2 + ((row >> 2) & 1);
        Vt[vb + vw +  0] = vv.x;
        Vt[vb + vw +  8] = vv.y;
        Vt[vb + vw + 16] = vv.z;
        Vt[vb + vw + 24] = vv.w;
    }
    __syncthreads();

    int qrow0 = half*256 + w*16;
    unsigned* Pw = Ps + w*1024;

    unsigned aq[4][4];
    {
        size_t r0 = (size_t)(gbase + qrow0 + lr)*NBIG + h*32;
        size_t r1 = (size_t)(gbase + qrow0 + lr + 8)*NBIG + h*32;
        #pragma unroll
        for (int s = 0; s < 4; s++) {
            aq[s][0] = __float_as_uint(g_big[r0 + s*8 + lc]);
            aq[s][1] = __float_as_uint(g_big[r1 + s*8 + lc]);
            aq[s][2] = __float_as_uint(g_big[r0 + s*8 + 4 + lc]);
            aq[s][3] = __float_as_uint(g_big[r1 + s*8 + 4 + lc]);
        }
    }

    float m0 = -1e30f, m1 = -1e30f, l0 = 0.f, l1 = 0.f;
    float oacc[4][4];
    #pragma unroll
    for (int nt = 0; nt < 4; nt++)
        #pragma unroll
        for (int q = 0; q < 4; q++) oacc[nt][q] = 0.f;

    int wbase = (4*lr + ((2*lc) & 3))*4 + ((lc >> 1) << 1);

    for (int j = 0; j < 4; j++) {
        int jb = j*128;
        float sacc[16][4];
        #pragma unroll
        for (int nt = 0; nt < 16; nt++)
            #pragma unroll
            for (int q = 0; q < 4; q++) sacc[nt][q] = 0.f;

        #pragma unroll
        for (int nt = 0; nt < 16; nt++) {
            int kb = ((jb >> 3) + nt) * 4;
            #pragma unroll
            for (int s = 0; s < 4; s++) {
                uint2 bv = *(const uint2*)&Ks[(kb + s)*64 + lane*2];
                mma_tf32(sacc[nt], aq[s], bv.x, bv.y);
            }
        }

        float cm0 = -1e30f, cm1 = -1e30f;
        #pragma unroll
        for (int nt = 0; nt < 16; nt++) {
            cm0 = fmaxf(cm0, fmaxf(sacc[nt][0], sacc[nt][1]));
            cm1 = fmaxf(cm1, fmaxf(sacc[nt][2], sacc[nt][3]));
        }
        cm0 = fmaxf(cm0, __shfl_xor_sync(0xffffffffu, cm0, 1));
        cm0 = fmaxf(cm0, __shfl_xor_sync(0xffffffffu, cm0, 2));
        cm1 = fmaxf(cm1, __shfl_xor_sync(0xffffffffu, cm1, 1));
        cm1 = fmaxf(cm1, __shfl_xor_sync(0xffffffffu, cm1, 2));

        float nm0 = fmaxf(m0, cm0), nm1 = fmaxf(m1, cm1);
        float sc0 = __expf((m0 - nm0) * SCALE), sc1 = __expf((m1 - nm1) * SCALE);
        m0 = nm0; m1 = nm1;
        #pragma unroll
        for (int nt = 0; nt < 4; nt++) {
            oacc[nt][0] *= sc0; oacc[nt][1] *= sc0;
            oacc[nt][2] *= sc1; oacc[nt][3] *= sc1;
        }

        float ps0 = 0.f, ps1 = 0.f;
        #pragma unroll
        for (int htg = 0; htg < 2; htg++) {
            #pragma unroll
            for (int ntl = 0; ntl < 8; ntl++) {
                int nt = htg*8 + ntl;
                float p0 = __expf((sacc[nt][0] - nm0) * SCALE);
                float p1 = __expf((sacc[nt][1] - nm0) * SCALE);
                float p2 = __expf((sacc[nt][2] - nm1) * SCALE);
                float p3 = __expf((sacc[nt][3] - nm1) * SCALE);
                ps0 += p0 + p1; ps1 += p2 + p3;
                int W = ntl*128 + wbase;
                uint2 q0 = { __float_as_uint(p0), __float_as_uint(p2) };
                uint2 q1 = { __float_as_uint(p1), __float_as_uint(p3) };
                *(uint2*)&Pw[W]     = q0;
                *(uint2*)&Pw[W + 4] = q1;
            }
            __syncwarp();
            #pragma unroll
            for (int s2 = 0; s2 < 8; s2++) {
                uint4 av = *(const uint4*)&Pw[s2*128 + lane*4];
                unsigned ap[4] = { av.x, av.y, av.z, av.w };
                int kblk = (jb + htg*64 + s2*8) >> 3;
                #pragma unroll
                for (int nt2 = 0; nt2 < 4; nt2++) {
                    uint2 bv = *(const uint2*)&Vt[(nt2*64 + kblk)*64 + lane*2];
                    mma_tf32(oacc[nt2], ap, bv.x, bv.y);
                }
            }
            __syncwarp();
        }
        ps0 += __shfl_xor_sync(0xffffffffu, ps0, 1);
        ps0 += __shfl_xor_sync(0xffffffffu, ps0, 2);
        ps1 += __shfl_xor_sync(0xffffffffu, ps1, 1);
        ps1 += __shfl_xor_sync(0xffffffffu, ps1, 2);
        l0 = l0 * sc0 + ps0;
        l1 = l1 * sc1 + ps1;
    }

    float inv0 = 1.0f / l0, inv1 = 1.0f / l1;
    int row0 = gbase + qrow0 + lr;
    #pragma unroll
    for (int nt2 = 0; nt2 < 4; nt2++) {
        int col = h*32 + nt2*8 + 2*lc;
        size_t wd = aperm(row0, col, HD);
        float2 p0 = { tf32round(oacc[nt2][0]*inv0), tf32round(oacc[nt2][2]*inv1) };
        float2 p1 = { tf32round(oacc[nt2][1]*inv0), tf32round(oacc[nt2][3]*inv1) };
        *(float2*)&g_attno[wd]     = p0;
        *(float2*)&g_attno[wd + 4] = p1;
    }
}

// ----------------------------- LN2 + combine (comb written A-perm) -----------------------------
__global__ void __launch_bounds__(256) k_combine(const float* __restrict__ g2, const float* __restrict__ be2,
                                                 const float* __restrict__ alpha_p)
{
    int w = threadIdx.x >> 5, lane = threadIdx.x & 31;
    int row = blockIdx.x * 8 + w;
    const float4* gr = (const float4*)&g_graw[(size_t)row*HD + lane*8];
    float4 a0 = gr[0], a1 = gr[1];
    float s = a0.x+a0.y+a0.z+a0.w + a1.x+a1.y+a1.z+a1.w;
    float mean = warpsum(s) * (1.0f/256.0f);
    float d[8] = { a0.x-mean, a0.y-mean, a0.z-mean, a0.w-mean,
                   a1.x-mean, a1.y-mean, a1.z-mean, a1.w-mean };
    float vs = 0.f;
    #pragma unroll
    for (int t = 0; t < 8; t++) vs += d[t]*d[t];
    float r = rsqrtf(warpsum(vs) * (1.0f/256.0f) + 1e-5f);
    float a = 1.0f / (1.0f + __expf(-alpha_p[0]));
    float oma = 1.0f - a;
    const float4* G2 = (const float4*)&g2[lane*8];
    const float4* B2 = (const float4*)&be2[lane*8];
    float4 gg0 = G2[0], gg1 = G2[1], bb0 = B2[0], bb1 = B2[1];
    const float4* loc = (const float4*)&g_local[(size_t)row*HD + lane*8];
    float4 l0 = loc[0], l1 = loc[1];
    float ov[8];
    ov[0] = a*l0.x + oma*(d[0]*r*gg0.x + bb0.x);
    ov[1] = a*l0.y + oma*(d[1]*r*gg0.y + bb0.y);
    ov[2] = a*l0.z + oma*(d[2]*r*gg0.z + bb0.z);
    ov[3] = a*l0.w + oma*(d[3]*r*gg0.w + bb0.w);
    ov[4] = a*l1.x + oma*(d[4]*r*gg1.x + bb1.x);
    ov[5] = a*l1.y + oma*(d[5]*r*gg1.y + bb1.y);
    ov[6] = a*l1.z + oma*(d[6]*r*gg1.z + bb1.z);
    ov[7] = a*l1.w + oma*(d[7]*r*gg1.w + bb1.w);
    size_t base = (size_t)((row >> 4) * 32 + lane) * 128;
    int rb = ((row & 7) * 4) * 4 + ((row >> 3) & 1);
    #pragma unroll
    for (int t = 0; t < 8; t++)
        g_comb[base + rb + (t & 3)*4 + ((t >> 2) << 1)] = tf32round(ov[t]);
}

// ----------------------------- residual + LN3 -> out (reads comb A-perm) -----------------------------
__global__ void __launch_bounds__(256) k_final(const float* __restrict__ g3, const float* __restrict__ be3,
                                               float* __restrict__ out)
{
    int w = threadIdx.x >> 5, lane = threadIdx.x & 31;
    int row = blockIdx.x * 8 + w;
    size_t base = (size_t)((row >> 4) * 32 + lane) * 128;
    int rb = ((row & 7) * 4) * 4 + ((row >> 3) & 1);
    float cv[8];
    #pragma unroll
    for (int t = 0; t < 8; t++)
        cv[t] = g_comb[base + rb + (t & 3)*4 + ((t >> 2) << 1)];
    const float4* f2 = (const float4*)&g_f2[(size_t)row*HD + lane*8];
    float4 e0 = f2[0], e1 = f2[1];
    float v[8] = { cv[0]+e0.x, cv[1]+e0.y, cv[2]+e0.z, cv[3]+e0.w,
                   cv[4]+e1.x, cv[5]+e1.y, cv[6]+e1.z, cv[7]+e1.w };
    float s = 0.f;
    #pragma unroll
    for (int t = 0; t < 8; t++) s += v[t];
    float mean = warpsum(s) * (1.0f/256.0f);
    float vs = 0.f;
    #pragma unroll
    for (int t = 0; t < 8; t++) { v[t] -= mean; vs += v[t]*v[t]; }
    float r = rsqrtf(warpsum(vs) * (1.0f/256.0f) + 1e-5f);
    const float4* G3 = (const float4*)&g3[lane*8];
    const float4* B3 = (const float4*)&be3[lane*8];
    float4 gg0 = G3[0], gg1 = G3[1], bb0 = B3[0], bb1 = B3[1];
    float4 o0, o1;
    o0.x = v[0]*r*gg0.x + bb0.x; o0.y = v[1]*r*gg0.y + bb0.y;
    o0.z = v[2]*r*gg0.z + bb0.z; o0.w = v[3]*r*gg0.w + bb0.w;
    o1.x = v[4]*r*gg1.x + bb1.x; o1.y = v[5]*r*gg1.y + bb1.y;
    o1.z = v[6]*r*gg1.z + bb1.z; o1.w = v[7]*r*gg1.w + bb1.w;
    float4* dst = (float4*)&out[(size_t)row*HD + lane*8];
    dst[0] = o0; dst[1] = o1;
}

// ----------------------------- launch -----------------------------
extern "C" void kernel_launch(void* const* d_in, const int* in_sizes, int n_in,
                              void* d_out, int out_size)
{
    const float* x        = (const float*)d_in[0];
    const float* ea       = (const float*)d_in[1];
    const float* W_l      = (const float*)d_in[2];
    const float* b_l      = (const float*)d_in[3];
    const float* W_r      = (const float*)d_in[4];
    const float* b_r      = (const float*)d_in[5];
    const float* W_e      = (const float*)d_in[6];
    const float* att      = (const float*)d_in[7];
    const float* bias_gat = (const float*)d_in[8];
    const float* ipw      = (const float*)d_in[9];
    const float* ipb      = (const float*)d_in[10];
    const float* opw      = (const float*)d_in[11];
    const float* opb      = (const float*)d_in[12];
    const float* alpha    = (const float*)d_in[13];
    const float* W1       = (const float*)d_in[14];
    const float* b1       = (const float*)d_in[15];
    const float* W2       = (const float*)d_in[16];
    const float* b2       = (const float*)d_in[17];
    const float* g1       = (const float*)d_in[18];
    const float* be1      = (const float*)d_in[19];
    const float* g2       = (const float*)d_in[20];
    const float* be2      = (const float*)d_in[21];
    const float* g3       = (const float*)d_in[22];
    const float* be3      = (const float*)d_in[23];
    const int*   ei       = (const int*)d_in[24];
    float* out = (float*)d_out;

    float *big, *attno, *graw, *comb, *h1, *f2;
    float *rx, *rbig, *ropw, *rw1, *rw2, *gbias;
    cudaGetSymbolAddress((void**)&big,   g_big);
    cudaGetSymbolAddress((void**)&attno, g_attno);
    cudaGetSymbolAddress((void**)&graw,  g_graw);
    cudaGetSymbolAddress((void**)&comb,  g_comb);
    cudaGetSymbolAddress((void**)&h1,    g_h1);
    cudaGetSymbolAddress((void**)&f2,    g_f2);
    cudaGetSymbolAddress((void**)&rx,    g_rx);
    cudaGetSymbolAddress((void**)&rbig,  g_rbig);
    cudaGetSymbolAddress((void**)&ropw,  g_ropw);
    cudaGetSymbolAddress((void**)&rw1,   g_rw1);
    cudaGetSymbolAddress((void**)&rw2,   g_rw2);
    cudaGetSymbolAddress((void**)&gbias, g_bias);

    cudaFuncSetAttribute(k_attn,   cudaFuncAttributeMaxDynamicSharedMemorySize, ATTN_SMEM_BYTES);
    cudaFuncSetAttribute(k_gemm_p, cudaFuncAttributeMaxDynamicSharedMemorySize, GEMM_SMEM);

    // fused producer path
    k_init<<<(NTOT + 255)/256, 256>>>(ipb, b_l, b_r);                                 // 0
    k_repa<<<(NTOT*HD/4 + 255)/256, 256>>>(x, rx, NTOT, HD);                          // 1
    k_repb<true ><<<(3*HD*HD/2 + 255)/256, 256>>>(ipw, rbig, 3*HD, HD, 0);            // 2
    k_repb<false><<<(HD*HD/2 + 255)/256, 256>>>(W_l, rbig, HD, HD, 768);              // 3
    k_repb<false><<<(HD*HD/2 + 255)/256, 256>>>(W_r, rbig, HD, HD, 1024);             // 4
    k_gemm_p<<<dim3(NBIG/128, NTOT/128), 256, GEMM_SMEM>>>(rx, rbig, gbias, big, NTOT, NBIG, HD, 0, 0, 0);  // 5: qkv|xl|xr

    // attention path
    k_attn<<<GRAPHS*HEADS*2, 512, ATTN_SMEM_BYTES>>>();
    k_repb<true><<<(HD*HD/2 + 255)/256, 256>>>(opw, ropw, HD, HD, 0);
    k_gemm_p<<<dim3(HD/128, NTOT/128), 256, GEMM_SMEM>>>(attno, ropw, opb, graw, NTOT, HD, HD, 0, 0, 0);

    // GAT path
    k_edgecnt<<<(EDG + 255)/256, 256>>>(ei, ea);
    k_scan<<<1, 1024>>>();
    k_fill<<<(EDG + 255)/256, 256>>>(ei);
    k_gat<<<NTOT/4, 256>>>(ei, ea, W_e, att, bias_gat, g1, be1);

    // combine + FFN + final LN
    k_combine<<<NTOT/8, 256>>>(g2, be2, alpha);
    k_repb<false><<<(HD*4*HD/2 + 255)/256, 256>>>(W1, rw1, 4*HD, HD, 0);
    k_repb<false><<<(4*HD*HD/2 + 255)/256, 256>>>(W2, rw2, HD, 4*HD, 0);
    k_gemm_p<<<dim3(4*HD/128, NTOT/128), 256, GEMM_SMEM>>>(comb, rw1, b1, h1, NTOT, 4*HD, HD, 1, 1, 1);
    k_gemm_p<<<dim3(HD/128, NTOT/128), 256, GEMM_SMEM>>>(h1, rw2, b2, f2, NTOT, HD, 4*HD, 0, 0, 0);
    k_final<<<NTOT/8, 256>>>(g3, be3, out);

    (void)in_sizes; (void)n_in; (void)out_size;
}